// round 13
// baseline (speedup 1.0000x reference)
#include <cuda_runtime.h>
#include <cuda_fp16.h>
#include <math.h>

// Problem constants
#define BB   8
#define NN   16384
#define KK   16
#define CC   64
#define MM   32
#define HH   32
#define HID  128
#define NPTS (BB*NN)          // 131072
#define BN_EPS 1e-5f

typedef unsigned long long u64;

__device__ __forceinline__ float gelu_exact(float y) {
    return 0.5f * y * (1.0f + erff(y * 0.70710678118654752f));
}

__device__ __forceinline__ unsigned h2u(__half2 h) { return *(unsigned*)&h; }
__device__ __forceinline__ __half2 u2h(unsigned u) { return *(__half2*)&u; }

__device__ __forceinline__ unsigned smem_u32(const void* p_) {
    unsigned r;
    asm("{ .reg .u64 t; cvta.to.shared.u64 t, %1; cvt.u32.u64 %0, t; }"
        : "=r"(r) : "l"(p_));
    return r;
}
__device__ __forceinline__ void cp_async16(unsigned saddr, const void* gptr) {
    asm volatile("cp.async.cg.shared.global [%0], [%1], 16;"
                 :: "r"(saddr), "l"(gptr));
}
#define CP_COMMIT() asm volatile("cp.async.commit_group;" ::: "memory")
#define CP_WAIT0()  asm volatile("cp.async.wait_group 0;" ::: "memory")

// Packed fp32x2 FMA
#define FFMA2(d,a,b,c) asm("fma.rn.f32x2 %0, %1, %2, %3;" : "=l"(d) : "l"(a), "l"(b), "l"(c))
#define PACK2(d,lo,hi) asm("mov.b64 %0, {%1, %2};" : "=l"(d) : "f"(lo), "f"(hi))
#define UNPK2(lo,hi,d) asm("mov.b64 {%0, %1}, %2;" : "=f"(lo), "=f"(hi) : "l"(d))
union F4 { float4 v; u64 p[2]; };

// m16n8k16 fp16 MMA, fp32 accumulate
__device__ __forceinline__ void mma16816(float d[4], const unsigned a[4],
                                         unsigned b0, unsigned b1) {
    asm volatile("mma.sync.aligned.m16n8k16.row.col.f32.f16.f16.f32 "
        "{%0,%1,%2,%3}, {%4,%5,%6,%7}, {%8,%9}, {%0,%1,%2,%3};"
        : "+f"(d[0]), "+f"(d[1]), "+f"(d[2]), "+f"(d[3])
        : "r"(a[0]), "r"(a[1]), "r"(a[2]), "r"(a[3]), "r"(b0), "r"(b1));
}

// Scratch
__device__ __half g_f12[(size_t)NPTS*128];
__device__ float  g_base[(size_t)NPTS*CC];

// Pre-converted weights + folded params (layouts as R12)
__device__ __half g_k1w[16384];
__device__ __half g_k2w[17920];
__device__ float  g_par1[1536];
__device__ float  g_par2[320];

struct P0 {
    const float *dirv, *de_w1, *de_g1, *de_b1, *de_m1, *de_v1, *de_w2, *de_bias2;
    const float *w1, *b1, *w2, *b2, *w3, *b3;
    const float *agg_g, *agg_b, *agg_m, *agg_v;
    const float *mw1, *mg, *mb, *mm, *mv, *mw2;
};

struct P1 { const float *f, *dp; };
struct P2 { const int* qidx; float* out; };

// ---------------------------------------------------------------------------
// Kernel 0: one-time weight conversion + BN folding.
// ---------------------------------------------------------------------------
__global__ void k0(P0 p) {
    const int tid = blockIdx.x*blockDim.x + threadIdx.x;
    const int stride = gridDim.x*blockDim.x;
    for (int idx = tid; idx < 4096; idx += stride) {
        int c = idx >> 6, i = idx & 63;
        g_k1w[c*72+i]         = __float2half(p.w1[idx]);
        g_k1w[4608 + c*72+i]  = __float2half(p.w2[idx]);
        g_k1w[9216 + c*72+i]  = __float2half(p.w3[idx]);
    }
    for (int idx = tid; idx < 2048; idx += stride) {
        int c = idx >> 5, h = idx & 31;
        g_k1w[13824 + c*40+h] = __float2half(p.de_w2[idx]);
    }
    for (int idx = tid; idx < 8192; idx += stride) {
        int j = idx >> 6, i = idx & 63;
        g_k2w[j*72 + i] = __float2half(p.mw1[idx]);
    }
    for (int idx = tid; idx < 8192; idx += stride) {
        int c = idx >> 7, j = idx & 127;
        g_k2w[9216 + c*136 + j] = __float2half(p.mw2[idx]);
    }
    for (int idx = tid; idx < 1024; idx += stride) {
        int m = idx >> 5, j = idx & 31;
        g_par1[m*32 + j] = p.de_w1[j*32 + m];
    }
    if (tid < 16) {
        int m0 = 2*tid, m1 = m0 + 1;
        float a0=p.dirv[m0*3], a1=p.dirv[m0*3+1], a2=p.dirv[m0*3+2];
        float ia = rsqrtf(fmaxf(a0*a0+a1*a1+a2*a2, 1e-24f));
        float b0=p.dirv[m1*3], b1=p.dirv[m1*3+1], b2=p.dirv[m1*3+2];
        float ib = rsqrtf(fmaxf(b0*b0+b1*b1+b2*b2, 1e-24f));
        unsigned* pv = (unsigned*)g_par1;
        pv[1024 + tid*3 + 0] = h2u(__floats2half2_rn(a0*ia, b0*ib));
        pv[1024 + tid*3 + 1] = h2u(__floats2half2_rn(a1*ia, b1*ib));
        pv[1024 + tid*3 + 2] = h2u(__floats2half2_rn(a2*ia, b2*ib));
    }
    if (tid >= 32 && tid < 96) {
        int c = tid - 32;
        g_par1[1088+c]=p.b1[c];
        g_par1[1152+c]=p.b2[c];
        g_par1[1216+c]=p.b3[c];
        g_par1[1280+c]=p.de_bias2[c];
        float sc = p.agg_g[c]*rsqrtf(p.agg_v[c]+BN_EPS);
        g_par1[1408+c]=sc;
        g_par1[1472+c]=p.agg_b[c]-p.agg_m[c]*sc;
        g_par2[256+c]=sc;
    }
    if (tid >= 96 && tid < 128) {
        int j = tid - 96;
        float sc = p.de_g1[j]*rsqrtf(p.de_v1[j]+BN_EPS);
        g_par1[1344+j]=sc;
        g_par1[1376+j]=p.de_b1[j]-p.de_m1[j]*sc;
    }
    if (tid >= 128 && tid < 256) {
        int j = tid - 128;
        float sc = p.mg[j]*rsqrtf(p.mv[j]+BN_EPS);
        g_par2[j]=sc;
        g_par2[128+j]=p.mb[j]-p.mm[j]*sc;
    }
}

// ---------------------------------------------------------------------------
// Kernel 1: 256 threads, 256 points / block, 2 blocks/SM. PDL secondary of k0:
// input-only prologue (dp normalize + x staging) runs concurrently with k0.
// ---------------------------------------------------------------------------
__global__ __launch_bounds__(256) void k1(P1 p) {
    extern __shared__ char smbase[];
    float*    sp     = (float*)smbase;
    float*    sdw1p  = sp;                    // [m*32+j] 1024
    unsigned* svvh   = (unsigned*)sp + 1024;  // 48
    float*    sb1    = sp + 1088;
    float*    sb2    = sp + 1152;
    float*    sb3    = sp + 1216;
    float*    sbias2 = sp + 1280;
    float*    ssc1   = sp + 1344;
    float*    ssh1   = sp + 1376;
    float*    sscA   = sp + 1408;
    float*    sshA   = sp + 1472;             // -> 1536 floats (6144 B)
    __half* xA  = (__half*)(smbase + 6144);   // 256*72
    __half* hA  = xA  + 18432;                // 256*40
    __half* ws1 = hA  + 10240;
    __half* ws2 = ws1 + 4608;
    __half* ws3 = ws2 + 4608;
    __half* dws = ws3 + 4608;                 // total 96256 B

    const int tid = threadIdx.x;
    const int p0 = blockIdx.x*256;
    const int b  = p0 >> 14;
    const int n0 = p0 & (NN-1);
    const int n  = n0 + tid;

    // ===== PROLOGUE: input-only work (overlaps k0 via PDL) =====
    unsigned X0[16], X1[16], X2[16];
    {
        const float4* dp4 = (const float4*)(p.dp + (size_t)b*3*NN*KK + (size_t)n*KK);
#pragma unroll
        for (int k4 = 0; k4 < 4; k4++) {
            float4 A = dp4[k4];
            float4 Bv= dp4[(NN*KK/4) + k4];
            float4 Cv= dp4[(2*NN*KK/4) + k4];
            float ax[4]={A.x,A.y,A.z,A.w}, bx[4]={Bv.x,Bv.y,Bv.z,Bv.w}, cx[4]={Cv.x,Cv.y,Cv.z,Cv.w};
#pragma unroll
            for (int kk = 0; kk < 4; kk++) {
                float x0=ax[kk], x1=bx[kk], x2=cx[kk];
                float inv = rsqrtf(fmaxf(x0*x0+x1*x1+x2*x2, 1e-24f));
                X0[4*k4+kk] = h2u(__float2half2_rn(x0*inv));
                X1[4*k4+kk] = h2u(__float2half2_rn(x1*inv));
                X2[4*k4+kk] = h2u(__float2half2_rn(x2*inv));
            }
        }
        const float* fb = p.f + (size_t)b*CC*NN + n;
#pragma unroll
        for (int c2 = 0; c2 < 32; c2++) {
            float v0 = fb[(size_t)(2*c2  )*NN];
            float v1 = fb[(size_t)(2*c2+1)*NN];
            *(unsigned*)&xA[tid*72 + 2*c2] = h2u(__floats2half2_rn(v0, v1));
        }
    }

    cudaGridDependencySynchronize();   // k0 outputs now visible

    // ===== stage weights (cp.async) + params =====
    {
        unsigned wd = smem_u32(ws1) + tid*16;
        const char* ws = (const char*)g_k1w + tid*16;
#pragma unroll
        for (int i = 0; i < 8; i++)
            cp_async16(wd + i*4096, ws + i*4096);
        CP_COMMIT();
        const float4* ps = (const float4*)g_par1;
        float4* pd = (float4*)sp;
        pd[tid] = ps[tid];
        if (tid < 128) pd[256+tid] = ps[256+tid];
    }
    __syncthreads();   // params visible; weights still in flight

    // ---- theta_max (packed fp16) + DE hidden MLP (FFMA2) ----
    {
        float tm[MM];
        const __half2 NEGH = __float2half2_rn(-65504.f);
#pragma unroll
        for (int pr = 0; pr < 16; pr++) {
            __half2 v0 = u2h(svvh[pr*3+0]);
            __half2 v1 = u2h(svvh[pr*3+1]);
            __half2 v2 = u2h(svvh[pr*3+2]);
            __half2 a = NEGH;
#pragma unroll
            for (int k = 0; k < KK; k++) {
                __half2 d = __hfma2(v2, u2h(X2[k]),
                             __hfma2(v1, u2h(X1[k]),
                              __hmul2(v0, u2h(X0[k]))));
                a = __hmax2(a, d);
            }
            float2 t = __half22float2(a);
            tm[2*pr] = t.x; tm[2*pr+1] = t.y;
        }

        u64 accp[16];
#pragma unroll
        for (int q = 0; q < 16; q++) accp[q] = 0ull;
#pragma unroll
        for (int m = 0; m < MM; m++) {
            u64 xd; PACK2(xd, tm[m], tm[m]);
            const float4* wrow = (const float4*)&sdw1p[m*32];
#pragma unroll
            for (int q4 = 0; q4 < 8; q4++) {
                F4 wv; wv.v = wrow[q4];
                FFMA2(accp[2*q4  ], wv.p[0], xd, accp[2*q4  ]);
                FFMA2(accp[2*q4+1], wv.p[1], xd, accp[2*q4+1]);
            }
        }
#pragma unroll
        for (int pr = 0; pr < 16; pr++) {
            float a0, a1; UNPK2(a0, a1, accp[pr]);
            int j0 = 2*pr;
            float y0 = a0*ssc1[j0  ] + ssh1[j0  ];
            float y1 = a1*ssc1[j0+1] + ssh1[j0+1];
            *(unsigned*)&hA[tid*40 + j0] =
                h2u(__floats2half2_rn(gelu_exact(y0), gelu_exact(y1)));
        }
    }

    CP_WAIT0();        // weights landed
    __syncthreads();

    const int w  = tid >> 5;
    const int lt = tid & 31;
    const int tq = lt >> 2;
    const int tr = lt & 3;
    const float* fg = p.f + (size_t)b*CC*NN;

#pragma unroll 1
    for (int pti = 0; pti < 2; pti++) {
        const int ptb = (w*2 + pti) * 16;
        unsigned ax[4][4], ah[2][4];
#pragma unroll
        for (int ks = 0; ks < 4; ks++) {
            int r0 = (ptb + tq)*72, r1 = r0 + 8*72;
            int k0v = 16*ks + 2*tr;
            ax[ks][0] = *(const unsigned*)&xA[r0 + k0v];
            ax[ks][1] = *(const unsigned*)&xA[r1 + k0v];
            ax[ks][2] = *(const unsigned*)&xA[r0 + k0v + 8];
            ax[ks][3] = *(const unsigned*)&xA[r1 + k0v + 8];
        }
#pragma unroll
        for (int ks = 0; ks < 2; ks++) {
            int r0 = (ptb + tq)*40, r1 = r0 + 8*40;
            int k0v = 16*ks + 2*tr;
            ah[ks][0] = *(const unsigned*)&hA[r0 + k0v];
            ah[ks][1] = *(const unsigned*)&hA[r1 + k0v];
            ah[ks][2] = *(const unsigned*)&hA[r0 + k0v + 8];
            ah[ks][3] = *(const unsigned*)&hA[r1 + k0v + 8];
        }

#pragma unroll 1
        for (int nt = 0; nt < 8; nt++) {
            const int ch0 = nt*8 + tr*2;
            float d1[4], d2[4], d3[4], dpe[4];
            d1[0]=sb1[ch0];   d1[1]=sb1[ch0+1];   d1[2]=d1[0];  d1[3]=d1[1];
            d2[0]=sb2[ch0];   d2[1]=sb2[ch0+1];   d2[2]=d2[0];  d2[3]=d2[1];
            d3[0]=sb3[ch0];   d3[1]=sb3[ch0+1];   d3[2]=d3[0];  d3[3]=d3[1];
            dpe[0]=sbias2[ch0]; dpe[1]=sbias2[ch0+1]; dpe[2]=dpe[0]; dpe[3]=dpe[1];

            const int nrow = (nt*8 + tq)*72;
#pragma unroll
            for (int ks = 0; ks < 4; ks++) {
                const int kb = 16*ks + 2*tr;
                unsigned b0, b1;
                b0 = *(const unsigned*)&ws1[nrow + kb];
                b1 = *(const unsigned*)&ws1[nrow + kb + 8];
                mma16816(d1, ax[ks], b0, b1);
                b0 = *(const unsigned*)&ws2[nrow + kb];
                b1 = *(const unsigned*)&ws2[nrow + kb + 8];
                mma16816(d2, ax[ks], b0, b1);
                b0 = *(const unsigned*)&ws3[nrow + kb];
                b1 = *(const unsigned*)&ws3[nrow + kb + 8];
                mma16816(d3, ax[ks], b0, b1);
            }
            const int drow = (nt*8 + tq)*40;
#pragma unroll
            for (int ks = 0; ks < 2; ks++) {
                const int kb = 16*ks + 2*tr;
                unsigned b0 = *(const unsigned*)&dws[drow + kb];
                unsigned b1 = *(const unsigned*)&dws[drow + kb + 8];
                mma16816(dpe, ah[ks], b0, b1);
            }

#pragma unroll
            for (int r = 0; r < 2; r++) {
                const int lpt = ptb + tq + 8*r;
                const int gpt = p0 + lpt;
                float f1a=d1[2*r], f1b=d1[2*r+1];
                float f2a=d2[2*r], f2b=d2[2*r+1];
                float f3a=d3[2*r], f3b=d3[2*r+1];
                float pea=dpe[2*r], peb=dpe[2*r+1];

                uint2 pk;
                pk.x = h2u(__floats2half2_rn(f1a, f1b));
                pk.y = h2u(__floats2half2_rn(f2a, f2b));
                *(uint2*)(g_f12 + (size_t)gpt*128 + 2*ch0) = pk;

                float fo0 = fg[(size_t)(ch0  )*NN + (n0 + lpt)];
                float fo1 = fg[(size_t)(ch0+1)*NN + (n0 + lpt)];
                float bx = fo0 + pea + sscA[ch0  ]*(f2a+f3a) + sshA[ch0  ];
                float by = fo1 + peb + sscA[ch0+1]*(f2b+f3b) + sshA[ch0+1];
                *(float2*)(g_base + (size_t)gpt*CC + ch0) = make_float2(bx, by);
            }
        }
    }
}

// ---------------------------------------------------------------------------
// Kernel 2: 64 points / block, 512 threads, 2 blocks/SM. PDL secondary of k1:
// weight/param staging (k0 outputs, transitively complete) runs in k1's tail.
// ---------------------------------------------------------------------------
__global__ __launch_bounds__(512, 2) void k2(P2 p) {
    extern __shared__ char smb[];
    float*  sxs  = (float*)smb;
    float*  sscM = sxs + 4352;
    float*  sshM = sscM + 128;
    float*  sA   = sshM + 128;                   // -> 18688 B
    __half* xh   = (__half*)(smb + 18688);
    __half* h2h  = xh + 4608;
    __half* w1h  = h2h + 8704;
    __half* w2h  = w1h + 9216;                   // -> 81152 B

    const int tid = threadIdx.x;
    const int w = tid >> 5, l = tid & 31;

    // ===== PROLOGUE (overlaps k1 via PDL; reads only inputs + k0 outputs) =====
    {
        unsigned wd = smem_u32(w1h) + tid*16;
        const char* ws = (const char*)g_k2w + tid*16;
#pragma unroll
        for (int i = 0; i < 4; i++)
            cp_async16(wd + i*8192, ws + i*8192);
        if (tid < 192) cp_async16(wd + 4*8192, ws + 4*8192);
        CP_COMMIT();
        const float4* ps = (const float4*)g_par2;
        float4* pd = (float4*)sscM;
        if (tid < 80) pd[tid] = ps[tid];
    }

    cudaGridDependencySynchronize();   // k1 outputs (g_f12/g_base) now visible
    __syncthreads();

    const int p0 = blockIdx.x*64;
    const int b  = p0 >> 14;
    const int n0 = p0 & (NN-1);

    // ---- Phase A: paired-point gather + edge max ----
    {
        const int half = (l >> 4) & 1;
        const int c    = l & 15;
        const size_t brow = (size_t)b*NN;
        const __half2 NEG = __float2half2_rn(-65504.f);
        const int lpA0 = w*4,     lp0 = lpA0 + half;
        const int lpA1 = w*4 + 2, lp1 = lpA1 + half;
        int jreg0 = p.qidx[(size_t)(p0 + lpA0)*KK + l];
        int jreg1 = p.qidx[(size_t)(p0 + lpA1)*KK + l];
        uint4 cv0 = *(const uint4*)(g_f12 + ((size_t)(p0+lp0) << 7) + c*8);
        uint4 cv1 = *(const uint4*)(g_f12 + ((size_t)(p0+lp1) << 7) + c*8);
        float4 bs0 = *(const float4*)(g_base + (size_t)(p0+lp0)*CC + 4*c);
        float4 bs1 = *(const float4*)(g_base + (size_t)(p0+lp1)*CC + 4*c);
        float4 sc = *(const float4*)&sA[4*c];
#pragma unroll
        for (int i = 0; i < 2; i++) {
            const int lp = (i == 0) ? lp0 : lp1;
            int jreg = (i == 0) ? jreg0 : jreg1;
            uint4 cv = (i == 0) ? cv0 : cv1;
            float4 bs = (i == 0) ? bs0 : bs1;
            __half2 m1a = NEG, m2a = NEG, m1b = NEG, m2b = NEG;
#pragma unroll
            for (int r = 0; r < KK; r++) {
                int j = __shfl_sync(0xffffffffu, jreg, (l & 16) + r);
                uint4 v = *(const uint4*)(g_f12 + ((brow + (size_t)j) << 7) + c*8);
                m1a = __hmax2(m1a, *(__half2*)&v.x);
                m2a = __hmax2(m2a, *(__half2*)&v.y);
                m1b = __hmax2(m1b, *(__half2*)&v.z);
                m2b = __hmax2(m2b, *(__half2*)&v.w);
            }
            float2 c1a = __half22float2(*(__half2*)&cv.x);
            float2 c2a = __half22float2(*(__half2*)&cv.y);
            float2 c1b = __half22float2(*(__half2*)&cv.z);
            float2 c2b = __half22float2(*(__half2*)&cv.w);
            float2 M1a = __half22float2(m1a), M2a = __half22float2(m2a);
            float2 M1b = __half22float2(m1b), M2b = __half22float2(m2b);
            float v0 = bs.x + sc.x*((M1a.x - c1a.x) + (M2a.x - c2a.x));
            float v1 = bs.y + sc.y*((M1a.y - c1a.y) + (M2a.y - c2a.y));
            float v2 = bs.z + sc.z*((M1b.x - c1b.x) + (M2b.x - c2b.x));
            float v3 = bs.w + sc.w*((M1b.y - c1b.y) + (M2b.y - c2b.y));
            *(float4*)&sxs[lp*68 + 4*c] = make_float4(v0,v1,v2,v3);
            uint2 xp;
            xp.x = h2u(__floats2half2_rn(v0, v1));
            xp.y = h2u(__floats2half2_rn(v2, v3));
            *(uint2*)&xh[lp*72 + 4*c] = xp;
        }
    }
    CP_WAIT0();
    __syncthreads();

    const int tq = l >> 2, tr = l & 3;

    // ---- Phase B: h2 = gelu(bnM(mw1 @ x)) via HMMA ----
    {
        const int pw = w & 3;
        const int nb = w >> 2;
        const int ptb = pw*16;
        unsigned ax[4][4];
#pragma unroll
        for (int ks = 0; ks < 4; ks++) {
            int r0 = (ptb + tq)*72, r1 = r0 + 8*72;
            int k0v = 16*ks + 2*tr;
            ax[ks][0] = *(const unsigned*)&xh[r0 + k0v];
            ax[ks][1] = *(const unsigned*)&xh[r1 + k0v];
            ax[ks][2] = *(const unsigned*)&xh[r0 + k0v + 8];
            ax[ks][3] = *(const unsigned*)&xh[r1 + k0v + 8];
        }
#pragma unroll
        for (int nt = 0; nt < 4; nt++) {
            const int jr = nb*32 + nt*8;
            float d[4] = {0.f,0.f,0.f,0.f};
            const int nrow = (jr + tq)*72;
#pragma unroll
            for (int ks = 0; ks < 4; ks++) {
                const int kb = 16*ks + 2*tr;
                unsigned b0 = *(const unsigned*)&w1h[nrow + kb];
                unsigned b1 = *(const unsigned*)&w1h[nrow + kb + 8];
                mma16816(d, ax[ks], b0, b1);
            }
            const int j0 = jr + 2*tr;
            float sc0 = sscM[j0], sh0 = sshM[j0];
            float sc1 = sscM[j0+1], sh1 = sshM[j0+1];
            float g0 = gelu_exact(d[0]*sc0 + sh0);
            float g1 = gelu_exact(d[1]*sc1 + sh1);
            float g2 = gelu_exact(d[2]*sc0 + sh0);
            float g3 = gelu_exact(d[3]*sc1 + sh1);
            *(unsigned*)&h2h[(ptb+tq  )*136 + j0] = h2u(__floats2half2_rn(g0, g1));
            *(unsigned*)&h2h[(ptb+tq+8)*136 + j0] = h2u(__floats2half2_rn(g2, g3));
        }
    }
    __syncthreads();

    // ---- Phase C: out = x + mw2 @ h2 via HMMA ----
    {
        const int pw = w & 3;
        const int cb = w >> 2;
        const int ptb = pw*16;
        const size_t obase = (size_t)b*CC*NN;
#pragma unroll
        for (int nt = 0; nt < 2; nt++) {
            const int ch = cb*16 + nt*8;
            float d[4] = {0.f,0.f,0.f,0.f};
            const int nrow = (ch + tq)*136;
#pragma unroll
            for (int ks = 0; ks < 8; ks++) {
                const int k0v = 16*ks + 2*tr;
                unsigned a[4];
                int r0 = (ptb + tq)*136, r1 = r0 + 8*136;
                a[0] = *(const unsigned*)&h2h[r0 + k0v];
                a[1] = *(const unsigned*)&h2h[r1 + k0v];
                a[2] = *(const unsigned*)&h2h[r0 + k0v + 8];
                a[3] = *(const unsigned*)&h2h[r1 + k0v + 8];
                unsigned b0 = *(const unsigned*)&w2h[nrow + k0v];
                unsigned b1 = *(const unsigned*)&w2h[nrow + k0v + 8];
                mma16816(d, a, b0, b1);
            }
            const int c0 = ch + 2*tr;
            float x00 = sxs[(ptb+tq  )*68 + c0];
            float x01 = sxs[(ptb+tq  )*68 + c0+1];
            float x10 = sxs[(ptb+tq+8)*68 + c0];
            float x11 = sxs[(ptb+tq+8)*68 + c0+1];
            p.out[obase + (size_t)(c0  )*NN + n0 + ptb+tq  ] = x00 + d[0];
            p.out[obase + (size_t)(c0+1)*NN + n0 + ptb+tq  ] = x01 + d[1];
            p.out[obase + (size_t)(c0  )*NN + n0 + ptb+tq+8] = x10 + d[2];
            p.out[obase + (size_t)(c0+1)*NN + n0 + ptb+tq+8] = x11 + d[3];
        }
    }
}

// ---------------------------------------------------------------------------
extern "C" void kernel_launch(void* const* d_in, const int* in_sizes, int n_in,
                              void* d_out, int out_size) {
    const float* f        = (const float*)d_in[0];
    const float* dp       = (const float*)d_in[1];
    const int*   qidx     = (const int*)  d_in[2];
    const float* dirv     = (const float*)d_in[3];
    const float* de_w1    = (const float*)d_in[4];
    const float* de_g1    = (const float*)d_in[5];
    const float* de_b1    = (const float*)d_in[6];
    const float* de_m1    = (const float*)d_in[7];
    const float* de_v1    = (const float*)d_in[8];
    const float* de_w2    = (const float*)d_in[9];
    const float* de_bias2 = (const float*)d_in[10];
    const float* w1       = (const float*)d_in[11];
    const float* b1       = (const float*)d_in[12];
    const float* w2       = (const float*)d_in[13];
    const float* b2       = (const float*)d_in[14];
    const float* w3       = (const float*)d_in[15];
    const float* b3       = (const float*)d_in[16];
    const float* agg_g    = (const float*)d_in[17];
    const float* agg_b    = (const float*)d_in[18];
    const float* agg_m    = (const float*)d_in[19];
    const float* agg_v    = (const float*)d_in[20];
    const float* mw1      = (const float*)d_in[21];
    const float* mg       = (const float*)d_in[22];
    const float* mb       = (const float*)d_in[23];
    const float* mm       = (const float*)d_in[24];
    const float* mv       = (const float*)d_in[25];
    const float* mw2      = (const float*)d_in[26];

    P0 p0;
    p0.dirv=dirv; p0.de_w1=de_w1; p0.de_g1=de_g1; p0.de_b1=de_b1; p0.de_m1=de_m1;
    p0.de_v1=de_v1; p0.de_w2=de_w2; p0.de_bias2=de_bias2;
    p0.w1=w1; p0.b1=b1; p0.w2=w2; p0.b2=b2; p0.w3=w3; p0.b3=b3;
    p0.agg_g=agg_g; p0.agg_b=agg_b; p0.agg_m=agg_m; p0.agg_v=agg_v;
    p0.mg=mg; p0.mb=mb; p0.mm=mm; p0.mv=mv; p0.mw1=mw1; p0.mw2=mw2;

    P1 p1; p1.f=f; p1.dp=dp;
    P2 p2; p2.qidx=qidx; p2.out=(float*)d_out;

    const size_t smem1 = 96256;   // bytes
    const size_t smem2 = 81152;   // bytes
    cudaFuncSetAttribute(k1, cudaFuncAttributeMaxDynamicSharedMemorySize, (int)smem1);
    cudaFuncSetAttribute(k2, cudaFuncAttributeMaxDynamicSharedMemorySize, (int)smem2);

    k0<<<128, 256>>>(p0);

    // k1 with PDL (overlaps k0)
    {
        cudaLaunchConfig_t cfg = {};
        cfg.gridDim = dim3(NPTS/256);
        cfg.blockDim = dim3(256);
        cfg.dynamicSmemBytes = smem1;
        cfg.stream = 0;
        cudaLaunchAttribute attr[1];
        attr[0].id = cudaLaunchAttributeProgrammaticStreamSerialization;
        attr[0].val.programmaticStreamSerializationAllowed = 1;
        cfg.attrs = attr;
        cfg.numAttrs = 1;
        cudaLaunchKernelEx(&cfg, k1, p1);
    }

    // k2 with PDL (overlaps k1 tail)
    {
        cudaLaunchConfig_t cfg = {};
        cfg.gridDim = dim3(NPTS/64);
        cfg.blockDim = dim3(512);
        cfg.dynamicSmemBytes = smem2;
        cfg.stream = 0;
        cudaLaunchAttribute attr[1];
        attr[0].id = cudaLaunchAttributeProgrammaticStreamSerialization;
        attr[0].val.programmaticStreamSerializationAllowed = 1;
        cfg.attrs = attr;
        cfg.numAttrs = 1;
        cudaLaunchKernelEx(&cfg, k2, p2);
    }
}

// round 14
// speedup vs baseline: 1.0002x; 1.0002x over previous
#include <cuda_runtime.h>
#include <cuda_fp16.h>
#include <math.h>

// Problem constants
#define BB   8
#define NN   16384
#define KK   16
#define CC   64
#define MM   32
#define HH   32
#define HID  128
#define NPTS (BB*NN)          // 131072
#define BN_EPS 1e-5f

typedef unsigned long long u64;

__device__ __forceinline__ float gelu_exact(float y) {
    return 0.5f * y * (1.0f + erff(y * 0.70710678118654752f));
}

__device__ __forceinline__ unsigned h2u(__half2 h) { return *(unsigned*)&h; }
__device__ __forceinline__ __half2 u2h(unsigned u) { return *(__half2*)&u; }

__device__ __forceinline__ unsigned smem_u32(const void* p_) {
    unsigned r;
    asm("{ .reg .u64 t; cvta.to.shared.u64 t, %1; cvt.u32.u64 %0, t; }"
        : "=r"(r) : "l"(p_));
    return r;
}
__device__ __forceinline__ void cp_async16(unsigned saddr, const void* gptr) {
    asm volatile("cp.async.cg.shared.global [%0], [%1], 16;"
                 :: "r"(saddr), "l"(gptr));
}
#define CP_COMMIT() asm volatile("cp.async.commit_group;" ::: "memory")
#define CP_WAIT0()  asm volatile("cp.async.wait_group 0;" ::: "memory")

// Packed fp32x2 FMA
#define FFMA2(d,a,b,c) asm("fma.rn.f32x2 %0, %1, %2, %3;" : "=l"(d) : "l"(a), "l"(b), "l"(c))
#define PACK2(d,lo,hi) asm("mov.b64 %0, {%1, %2};" : "=l"(d) : "f"(lo), "f"(hi))
#define UNPK2(lo,hi,d) asm("mov.b64 {%0, %1}, %2;" : "=f"(lo), "=f"(hi) : "l"(d))
union F4 { float4 v; u64 p[2]; };

// m16n8k16 fp16 MMA, fp32 accumulate
__device__ __forceinline__ void mma16816(float d[4], const unsigned a[4],
                                         unsigned b0, unsigned b1) {
    asm volatile("mma.sync.aligned.m16n8k16.row.col.f32.f16.f16.f32 "
        "{%0,%1,%2,%3}, {%4,%5,%6,%7}, {%8,%9}, {%0,%1,%2,%3};"
        : "+f"(d[0]), "+f"(d[1]), "+f"(d[2]), "+f"(d[3])
        : "r"(a[0]), "r"(a[1]), "r"(a[2]), "r"(a[3]), "r"(b0), "r"(b1));
}

// Scratch
__device__ __half g_f12[(size_t)NPTS*128];
__device__ float  g_base[(size_t)NPTS*CC];

// Pre-converted weights + folded params (layouts as R12)
__device__ __half g_k1w[16384];
__device__ __half g_k2w[17920];
__device__ float  g_par1[1536];
__device__ float  g_par2[320];

struct P0 {
    const float *dirv, *de_w1, *de_g1, *de_b1, *de_m1, *de_v1, *de_w2, *de_bias2;
    const float *w1, *b1, *w2, *b2, *w3, *b3;
    const float *agg_g, *agg_b, *agg_m, *agg_v;
    const float *mw1, *mg, *mb, *mm, *mv, *mw2;
};

struct P1 { const float *f, *dp; };
struct P2 { const int* qidx; float* out; };

// ---------------------------------------------------------------------------
// Kernel 0: one-time weight conversion + BN folding.
// Triggers PDL completion at entry: k1 (whose prologue reads only kernel
// inputs) may launch and run concurrently; k1 gates on GridDependencySync.
// ---------------------------------------------------------------------------
__global__ void k0(P0 p) {
    cudaTriggerProgrammaticLaunchCompletion();
    const int tid = blockIdx.x*blockDim.x + threadIdx.x;
    const int stride = gridDim.x*blockDim.x;
    for (int idx = tid; idx < 4096; idx += stride) {
        int c = idx >> 6, i = idx & 63;
        g_k1w[c*72+i]         = __float2half(p.w1[idx]);
        g_k1w[4608 + c*72+i]  = __float2half(p.w2[idx]);
        g_k1w[9216 + c*72+i]  = __float2half(p.w3[idx]);
    }
    for (int idx = tid; idx < 2048; idx += stride) {
        int c = idx >> 5, h = idx & 31;
        g_k1w[13824 + c*40+h] = __float2half(p.de_w2[idx]);
    }
    for (int idx = tid; idx < 8192; idx += stride) {
        int j = idx >> 6, i = idx & 63;
        g_k2w[j*72 + i] = __float2half(p.mw1[idx]);
    }
    for (int idx = tid; idx < 8192; idx += stride) {
        int c = idx >> 7, j = idx & 127;
        g_k2w[9216 + c*136 + j] = __float2half(p.mw2[idx]);
    }
    for (int idx = tid; idx < 1024; idx += stride) {
        int m = idx >> 5, j = idx & 31;
        g_par1[m*32 + j] = p.de_w1[j*32 + m];
    }
    if (tid < 16) {
        int m0 = 2*tid, m1 = m0 + 1;
        float a0=p.dirv[m0*3], a1=p.dirv[m0*3+1], a2=p.dirv[m0*3+2];
        float ia = rsqrtf(fmaxf(a0*a0+a1*a1+a2*a2, 1e-24f));
        float b0=p.dirv[m1*3], b1=p.dirv[m1*3+1], b2=p.dirv[m1*3+2];
        float ib = rsqrtf(fmaxf(b0*b0+b1*b1+b2*b2, 1e-24f));
        unsigned* pv = (unsigned*)g_par1;
        pv[1024 + tid*3 + 0] = h2u(__floats2half2_rn(a0*ia, b0*ib));
        pv[1024 + tid*3 + 1] = h2u(__floats2half2_rn(a1*ia, b1*ib));
        pv[1024 + tid*3 + 2] = h2u(__floats2half2_rn(a2*ia, b2*ib));
    }
    if (tid >= 32 && tid < 96) {
        int c = tid - 32;
        g_par1[1088+c]=p.b1[c];
        g_par1[1152+c]=p.b2[c];
        g_par1[1216+c]=p.b3[c];
        g_par1[1280+c]=p.de_bias2[c];
        float sc = p.agg_g[c]*rsqrtf(p.agg_v[c]+BN_EPS);
        g_par1[1408+c]=sc;
        g_par1[1472+c]=p.agg_b[c]-p.agg_m[c]*sc;
        g_par2[256+c]=sc;
    }
    if (tid >= 96 && tid < 128) {
        int j = tid - 96;
        float sc = p.de_g1[j]*rsqrtf(p.de_v1[j]+BN_EPS);
        g_par1[1344+j]=sc;
        g_par1[1376+j]=p.de_b1[j]-p.de_m1[j]*sc;
    }
    if (tid >= 128 && tid < 256) {
        int j = tid - 128;
        float sc = p.mg[j]*rsqrtf(p.mv[j]+BN_EPS);
        g_par2[j]=sc;
        g_par2[128+j]=p.mb[j]-p.mm[j]*sc;
    }
}

// ---------------------------------------------------------------------------
// Kernel 1: 256 threads, 256 points / block, 2 blocks/SM. PDL secondary of k0:
// input-only prologue overlaps k0; triggers k2's launch after its own
// dependency sync (k0 then provably complete for k2's prologue reads).
// ---------------------------------------------------------------------------
__global__ __launch_bounds__(256) void k1(P1 p) {
    extern __shared__ char smbase[];
    float*    sp     = (float*)smbase;
    float*    sdw1p  = sp;                    // [m*32+j] 1024
    unsigned* svvh   = (unsigned*)sp + 1024;  // 48
    float*    sb1    = sp + 1088;
    float*    sb2    = sp + 1152;
    float*    sb3    = sp + 1216;
    float*    sbias2 = sp + 1280;
    float*    ssc1   = sp + 1344;
    float*    ssh1   = sp + 1376;
    float*    sscA   = sp + 1408;
    float*    sshA   = sp + 1472;             // -> 1536 floats (6144 B)
    __half* xA  = (__half*)(smbase + 6144);   // 256*72
    __half* hA  = xA  + 18432;                // 256*40
    __half* ws1 = hA  + 10240;
    __half* ws2 = ws1 + 4608;
    __half* ws3 = ws2 + 4608;
    __half* dws = ws3 + 4608;                 // total 96256 B

    const int tid = threadIdx.x;
    const int p0 = blockIdx.x*256;
    const int b  = p0 >> 14;
    const int n0 = p0 & (NN-1);
    const int n  = n0 + tid;

    // ===== PROLOGUE: input-only work (overlaps k0 via PDL) =====
    unsigned X0[16], X1[16], X2[16];
    {
        const float4* dp4 = (const float4*)(p.dp + (size_t)b*3*NN*KK + (size_t)n*KK);
#pragma unroll
        for (int k4 = 0; k4 < 4; k4++) {
            float4 A = dp4[k4];
            float4 Bv= dp4[(NN*KK/4) + k4];
            float4 Cv= dp4[(2*NN*KK/4) + k4];
            float ax[4]={A.x,A.y,A.z,A.w}, bx[4]={Bv.x,Bv.y,Bv.z,Bv.w}, cx[4]={Cv.x,Cv.y,Cv.z,Cv.w};
#pragma unroll
            for (int kk = 0; kk < 4; kk++) {
                float x0=ax[kk], x1=bx[kk], x2=cx[kk];
                float inv = rsqrtf(fmaxf(x0*x0+x1*x1+x2*x2, 1e-24f));
                X0[4*k4+kk] = h2u(__float2half2_rn(x0*inv));
                X1[4*k4+kk] = h2u(__float2half2_rn(x1*inv));
                X2[4*k4+kk] = h2u(__float2half2_rn(x2*inv));
            }
        }
        const float* fb = p.f + (size_t)b*CC*NN + n;
#pragma unroll
        for (int c2 = 0; c2 < 32; c2++) {
            float v0 = fb[(size_t)(2*c2  )*NN];
            float v1 = fb[(size_t)(2*c2+1)*NN];
            *(unsigned*)&xA[tid*72 + 2*c2] = h2u(__floats2half2_rn(v0, v1));
        }
    }

    cudaGridDependencySynchronize();   // k0 outputs now visible
    cudaTriggerProgrammaticLaunchCompletion();  // let k2 launch (k0 done)

    // ===== stage weights (cp.async) + params =====
    {
        unsigned wd = smem_u32(ws1) + tid*16;
        const char* ws = (const char*)g_k1w + tid*16;
#pragma unroll
        for (int i = 0; i < 8; i++)
            cp_async16(wd + i*4096, ws + i*4096);
        CP_COMMIT();
        const float4* ps = (const float4*)g_par1;
        float4* pd = (float4*)sp;
        pd[tid] = ps[tid];
        if (tid < 128) pd[256+tid] = ps[256+tid];
    }
    __syncthreads();   // params visible; weights still in flight

    // ---- theta_max (packed fp16) + DE hidden MLP (FFMA2) ----
    {
        float tm[MM];
        const __half2 NEGH = __float2half2_rn(-65504.f);
#pragma unroll
        for (int pr = 0; pr < 16; pr++) {
            __half2 v0 = u2h(svvh[pr*3+0]);
            __half2 v1 = u2h(svvh[pr*3+1]);
            __half2 v2 = u2h(svvh[pr*3+2]);
            __half2 a = NEGH;
#pragma unroll
            for (int k = 0; k < KK; k++) {
                __half2 d = __hfma2(v2, u2h(X2[k]),
                             __hfma2(v1, u2h(X1[k]),
                              __hmul2(v0, u2h(X0[k]))));
                a = __hmax2(a, d);
            }
            float2 t = __half22float2(a);
            tm[2*pr] = t.x; tm[2*pr+1] = t.y;
        }

        u64 accp[16];
#pragma unroll
        for (int q = 0; q < 16; q++) accp[q] = 0ull;
#pragma unroll
        for (int m = 0; m < MM; m++) {
            u64 xd; PACK2(xd, tm[m], tm[m]);
            const float4* wrow = (const float4*)&sdw1p[m*32];
#pragma unroll
            for (int q4 = 0; q4 < 8; q4++) {
                F4 wv; wv.v = wrow[q4];
                FFMA2(accp[2*q4  ], wv.p[0], xd, accp[2*q4  ]);
                FFMA2(accp[2*q4+1], wv.p[1], xd, accp[2*q4+1]);
            }
        }
#pragma unroll
        for (int pr = 0; pr < 16; pr++) {
            float a0, a1; UNPK2(a0, a1, accp[pr]);
            int j0 = 2*pr;
            float y0 = a0*ssc1[j0  ] + ssh1[j0  ];
            float y1 = a1*ssc1[j0+1] + ssh1[j0+1];
            *(unsigned*)&hA[tid*40 + j0] =
                h2u(__floats2half2_rn(gelu_exact(y0), gelu_exact(y1)));
        }
    }

    CP_WAIT0();        // weights landed
    __syncthreads();

    const int w  = tid >> 5;
    const int lt = tid & 31;
    const int tq = lt >> 2;
    const int tr = lt & 3;
    const float* fg = p.f + (size_t)b*CC*NN;

#pragma unroll 1
    for (int pti = 0; pti < 2; pti++) {
        const int ptb = (w*2 + pti) * 16;
        unsigned ax[4][4], ah[2][4];
#pragma unroll
        for (int ks = 0; ks < 4; ks++) {
            int r0 = (ptb + tq)*72, r1 = r0 + 8*72;
            int k0v = 16*ks + 2*tr;
            ax[ks][0] = *(const unsigned*)&xA[r0 + k0v];
            ax[ks][1] = *(const unsigned*)&xA[r1 + k0v];
            ax[ks][2] = *(const unsigned*)&xA[r0 + k0v + 8];
            ax[ks][3] = *(const unsigned*)&xA[r1 + k0v + 8];
        }
#pragma unroll
        for (int ks = 0; ks < 2; ks++) {
            int r0 = (ptb + tq)*40, r1 = r0 + 8*40;
            int k0v = 16*ks + 2*tr;
            ah[ks][0] = *(const unsigned*)&hA[r0 + k0v];
            ah[ks][1] = *(const unsigned*)&hA[r1 + k0v];
            ah[ks][2] = *(const unsigned*)&hA[r0 + k0v + 8];
            ah[ks][3] = *(const unsigned*)&hA[r1 + k0v + 8];
        }

#pragma unroll 1
        for (int nt = 0; nt < 8; nt++) {
            const int ch0 = nt*8 + tr*2;
            float d1[4], d2[4], d3[4], dpe[4];
            d1[0]=sb1[ch0];   d1[1]=sb1[ch0+1];   d1[2]=d1[0];  d1[3]=d1[1];
            d2[0]=sb2[ch0];   d2[1]=sb2[ch0+1];   d2[2]=d2[0];  d2[3]=d2[1];
            d3[0]=sb3[ch0];   d3[1]=sb3[ch0+1];   d3[2]=d3[0];  d3[3]=d3[1];
            dpe[0]=sbias2[ch0]; dpe[1]=sbias2[ch0+1]; dpe[2]=dpe[0]; dpe[3]=dpe[1];

            const int nrow = (nt*8 + tq)*72;
#pragma unroll
            for (int ks = 0; ks < 4; ks++) {
                const int kb = 16*ks + 2*tr;
                unsigned b0, b1;
                b0 = *(const unsigned*)&ws1[nrow + kb];
                b1 = *(const unsigned*)&ws1[nrow + kb + 8];
                mma16816(d1, ax[ks], b0, b1);
                b0 = *(const unsigned*)&ws2[nrow + kb];
                b1 = *(const unsigned*)&ws2[nrow + kb + 8];
                mma16816(d2, ax[ks], b0, b1);
                b0 = *(const unsigned*)&ws3[nrow + kb];
                b1 = *(const unsigned*)&ws3[nrow + kb + 8];
                mma16816(d3, ax[ks], b0, b1);
            }
            const int drow = (nt*8 + tq)*40;
#pragma unroll
            for (int ks = 0; ks < 2; ks++) {
                const int kb = 16*ks + 2*tr;
                unsigned b0 = *(const unsigned*)&dws[drow + kb];
                unsigned b1 = *(const unsigned*)&dws[drow + kb + 8];
                mma16816(dpe, ah[ks], b0, b1);
            }

#pragma unroll
            for (int r = 0; r < 2; r++) {
                const int lpt = ptb + tq + 8*r;
                const int gpt = p0 + lpt;
                float f1a=d1[2*r], f1b=d1[2*r+1];
                float f2a=d2[2*r], f2b=d2[2*r+1];
                float f3a=d3[2*r], f3b=d3[2*r+1];
                float pea=dpe[2*r], peb=dpe[2*r+1];

                uint2 pk;
                pk.x = h2u(__floats2half2_rn(f1a, f1b));
                pk.y = h2u(__floats2half2_rn(f2a, f2b));
                *(uint2*)(g_f12 + (size_t)gpt*128 + 2*ch0) = pk;

                float fo0 = fg[(size_t)(ch0  )*NN + (n0 + lpt)];
                float fo1 = fg[(size_t)(ch0+1)*NN + (n0 + lpt)];
                float bx = fo0 + pea + sscA[ch0  ]*(f2a+f3a) + sshA[ch0  ];
                float by = fo1 + peb + sscA[ch0+1]*(f2b+f3b) + sshA[ch0+1];
                *(float2*)(g_base + (size_t)gpt*CC + ch0) = make_float2(bx, by);
            }
        }
    }
}

// ---------------------------------------------------------------------------
// Kernel 2: 64 points / block, 512 threads, 2 blocks/SM. PDL secondary of k1:
// weight/param staging (k0 outputs, complete once k1 triggered) overlaps k1.
// ---------------------------------------------------------------------------
__global__ __launch_bounds__(512, 2) void k2(P2 p) {
    extern __shared__ char smb[];
    float*  sxs  = (float*)smb;
    float*  sscM = sxs + 4352;
    float*  sshM = sscM + 128;
    float*  sA   = sshM + 128;                   // -> 18688 B
    __half* xh   = (__half*)(smb + 18688);
    __half* h2h  = xh + 4608;
    __half* w1h  = h2h + 8704;
    __half* w2h  = w1h + 9216;                   // -> 81152 B

    const int tid = threadIdx.x;
    const int w = tid >> 5, l = tid & 31;

    // ===== PROLOGUE (overlaps k1 via PDL; reads only inputs + k0 outputs) =====
    {
        unsigned wd = smem_u32(w1h) + tid*16;
        const char* ws = (const char*)g_k2w + tid*16;
#pragma unroll
        for (int i = 0; i < 4; i++)
            cp_async16(wd + i*8192, ws + i*8192);
        if (tid < 192) cp_async16(wd + 4*8192, ws + 4*8192);
        CP_COMMIT();
        const float4* ps = (const float4*)g_par2;
        float4* pd = (float4*)sscM;
        if (tid < 80) pd[tid] = ps[tid];
    }

    cudaGridDependencySynchronize();   // k1 outputs (g_f12/g_base) now visible
    __syncthreads();

    const int p0 = blockIdx.x*64;
    const int b  = p0 >> 14;
    const int n0 = p0 & (NN-1);

    // ---- Phase A: paired-point gather + edge max ----
    {
        const int half = (l >> 4) & 1;
        const int c    = l & 15;
        const size_t brow = (size_t)b*NN;
        const __half2 NEG = __float2half2_rn(-65504.f);
        const int lpA0 = w*4,     lp0 = lpA0 + half;
        const int lpA1 = w*4 + 2, lp1 = lpA1 + half;
        int jreg0 = p.qidx[(size_t)(p0 + lpA0)*KK + l];
        int jreg1 = p.qidx[(size_t)(p0 + lpA1)*KK + l];
        uint4 cv0 = *(const uint4*)(g_f12 + ((size_t)(p0+lp0) << 7) + c*8);
        uint4 cv1 = *(const uint4*)(g_f12 + ((size_t)(p0+lp1) << 7) + c*8);
        float4 bs0 = *(const float4*)(g_base + (size_t)(p0+lp0)*CC + 4*c);
        float4 bs1 = *(const float4*)(g_base + (size_t)(p0+lp1)*CC + 4*c);
        float4 sc = *(const float4*)&sA[4*c];
#pragma unroll
        for (int i = 0; i < 2; i++) {
            const int lp = (i == 0) ? lp0 : lp1;
            int jreg = (i == 0) ? jreg0 : jreg1;
            uint4 cv = (i == 0) ? cv0 : cv1;
            float4 bs = (i == 0) ? bs0 : bs1;
            __half2 m1a = NEG, m2a = NEG, m1b = NEG, m2b = NEG;
#pragma unroll
            for (int r = 0; r < KK; r++) {
                int j = __shfl_sync(0xffffffffu, jreg, (l & 16) + r);
                uint4 v = *(const uint4*)(g_f12 + ((brow + (size_t)j) << 7) + c*8);
                m1a = __hmax2(m1a, *(__half2*)&v.x);
                m2a = __hmax2(m2a, *(__half2*)&v.y);
                m1b = __hmax2(m1b, *(__half2*)&v.z);
                m2b = __hmax2(m2b, *(__half2*)&v.w);
            }
            float2 c1a = __half22float2(*(__half2*)&cv.x);
            float2 c2a = __half22float2(*(__half2*)&cv.y);
            float2 c1b = __half22float2(*(__half2*)&cv.z);
            float2 c2b = __half22float2(*(__half2*)&cv.w);
            float2 M1a = __half22float2(m1a), M2a = __half22float2(m2a);
            float2 M1b = __half22float2(m1b), M2b = __half22float2(m2b);
            float v0 = bs.x + sc.x*((M1a.x - c1a.x) + (M2a.x - c2a.x));
            float v1 = bs.y + sc.y*((M1a.y - c1a.y) + (M2a.y - c2a.y));
            float v2 = bs.z + sc.z*((M1b.x - c1b.x) + (M2b.x - c2b.x));
            float v3 = bs.w + sc.w*((M1b.y - c1b.y) + (M2b.y - c2b.y));
            *(float4*)&sxs[lp*68 + 4*c] = make_float4(v0,v1,v2,v3);
            uint2 xp;
            xp.x = h2u(__floats2half2_rn(v0, v1));
            xp.y = h2u(__floats2half2_rn(v2, v3));
            *(uint2*)&xh[lp*72 + 4*c] = xp;
        }
    }
    CP_WAIT0();
    __syncthreads();

    const int tq = l >> 2, tr = l & 3;

    // ---- Phase B: h2 = gelu(bnM(mw1 @ x)) via HMMA ----
    {
        const int pw = w & 3;
        const int nb = w >> 2;
        const int ptb = pw*16;
        unsigned ax[4][4];
#pragma unroll
        for (int ks = 0; ks < 4; ks++) {
            int r0 = (ptb + tq)*72, r1 = r0 + 8*72;
            int k0v = 16*ks + 2*tr;
            ax[ks][0] = *(const unsigned*)&xh[r0 + k0v];
            ax[ks][1] = *(const unsigned*)&xh[r1 + k0v];
            ax[ks][2] = *(const unsigned*)&xh[r0 + k0v + 8];
            ax[ks][3] = *(const unsigned*)&xh[r1 + k0v + 8];
        }
#pragma unroll
        for (int nt = 0; nt < 4; nt++) {
            const int jr = nb*32 + nt*8;
            float d[4] = {0.f,0.f,0.f,0.f};
            const int nrow = (jr + tq)*72;
#pragma unroll
            for (int ks = 0; ks < 4; ks++) {
                const int kb = 16*ks + 2*tr;
                unsigned b0 = *(const unsigned*)&w1h[nrow + kb];
                unsigned b1 = *(const unsigned*)&w1h[nrow + kb + 8];
                mma16816(d, ax[ks], b0, b1);
            }
            const int j0 = jr + 2*tr;
            float sc0 = sscM[j0], sh0 = sshM[j0];
            float sc1 = sscM[j0+1], sh1 = sshM[j0+1];
            float g0 = gelu_exact(d[0]*sc0 + sh0);
            float g1 = gelu_exact(d[1]*sc1 + sh1);
            float g2 = gelu_exact(d[2]*sc0 + sh0);
            float g3 = gelu_exact(d[3]*sc1 + sh1);
            *(unsigned*)&h2h[(ptb+tq  )*136 + j0] = h2u(__floats2half2_rn(g0, g1));
            *(unsigned*)&h2h[(ptb+tq+8)*136 + j0] = h2u(__floats2half2_rn(g2, g3));
        }
    }
    __syncthreads();

    // ---- Phase C: out = x + mw2 @ h2 via HMMA ----
    {
        const int pw = w & 3;
        const int cb = w >> 2;
        const int ptb = pw*16;
        const size_t obase = (size_t)b*CC*NN;
#pragma unroll
        for (int nt = 0; nt < 2; nt++) {
            const int ch = cb*16 + nt*8;
            float d[4] = {0.f,0.f,0.f,0.f};
            const int nrow = (ch + tq)*136;
#pragma unroll
            for (int ks = 0; ks < 8; ks++) {
                const int k0v = 16*ks + 2*tr;
                unsigned a[4];
                int r0 = (ptb + tq)*136, r1 = r0 + 8*136;
                a[0] = *(const unsigned*)&h2h[r0 + k0v];
                a[1] = *(const unsigned*)&h2h[r1 + k0v];
                a[2] = *(const unsigned*)&h2h[r0 + k0v + 8];
                a[3] = *(const unsigned*)&h2h[r1 + k0v + 8];
                unsigned b0 = *(const unsigned*)&w2h[nrow + k0v];
                unsigned b1 = *(const unsigned*)&w2h[nrow + k0v + 8];
                mma16816(d, a, b0, b1);
            }
            const int c0 = ch + 2*tr;
            float x00 = sxs[(ptb+tq  )*68 + c0];
            float x01 = sxs[(ptb+tq  )*68 + c0+1];
            float x10 = sxs[(ptb+tq+8)*68 + c0];
            float x11 = sxs[(ptb+tq+8)*68 + c0+1];
            p.out[obase + (size_t)(c0  )*NN + n0 + ptb+tq  ] = x00 + d[0];
            p.out[obase + (size_t)(c0+1)*NN + n0 + ptb+tq  ] = x01 + d[1];
            p.out[obase + (size_t)(c0  )*NN + n0 + ptb+tq+8] = x10 + d[2];
            p.out[obase + (size_t)(c0+1)*NN + n0 + ptb+tq+8] = x11 + d[3];
        }
    }
}

// ---------------------------------------------------------------------------
extern "C" void kernel_launch(void* const* d_in, const int* in_sizes, int n_in,
                              void* d_out, int out_size) {
    const float* f        = (const float*)d_in[0];
    const float* dp       = (const float*)d_in[1];
    const int*   qidx     = (const int*)  d_in[2];
    const float* dirv     = (const float*)d_in[3];
    const float* de_w1    = (const float*)d_in[4];
    const float* de_g1    = (const float*)d_in[5];
    const float* de_b1    = (const float*)d_in[6];
    const float* de_m1    = (const float*)d_in[7];
    const float* de_v1    = (const float*)d_in[8];
    const float* de_w2    = (const float*)d_in[9];
    const float* de_bias2 = (const float*)d_in[10];
    const float* w1       = (const float*)d_in[11];
    const float* b1       = (const float*)d_in[12];
    const float* w2       = (const float*)d_in[13];
    const float* b2       = (const float*)d_in[14];
    const float* w3       = (const float*)d_in[15];
    const float* b3       = (const float*)d_in[16];
    const float* agg_g    = (const float*)d_in[17];
    const float* agg_b    = (const float*)d_in[18];
    const float* agg_m    = (const float*)d_in[19];
    const float* agg_v    = (const float*)d_in[20];
    const float* mw1      = (const float*)d_in[21];
    const float* mg       = (const float*)d_in[22];
    const float* mb       = (const float*)d_in[23];
    const float* mm       = (const float*)d_in[24];
    const float* mv       = (const float*)d_in[25];
    const float* mw2      = (const float*)d_in[26];

    P0 p0;
    p0.dirv=dirv; p0.de_w1=de_w1; p0.de_g1=de_g1; p0.de_b1=de_b1; p0.de_m1=de_m1;
    p0.de_v1=de_v1; p0.de_w2=de_w2; p0.de_bias2=de_bias2;
    p0.w1=w1; p0.b1=b1; p0.w2=w2; p0.b2=b2; p0.w3=w3; p0.b3=b3;
    p0.agg_g=agg_g; p0.agg_b=agg_b; p0.agg_m=agg_m; p0.agg_v=agg_v;
    p0.mg=mg; p0.mb=mb; p0.mm=mm; p0.mv=mv; p0.mw1=mw1; p0.mw2=mw2;

    P1 p1; p1.f=f; p1.dp=dp;
    P2 p2; p2.qidx=qidx; p2.out=(float*)d_out;

    const size_t smem1 = 96256;   // bytes
    const size_t smem2 = 81152;   // bytes
    cudaFuncSetAttribute(k1, cudaFuncAttributeMaxDynamicSharedMemorySize, (int)smem1);
    cudaFuncSetAttribute(k2, cudaFuncAttributeMaxDynamicSharedMemorySize, (int)smem2);

    k0<<<128, 256>>>(p0);

    // k1 with PDL (overlaps k0 — k0 triggers at entry)
    {
        cudaLaunchConfig_t cfg = {};
        cfg.gridDim = dim3(NPTS/256);
        cfg.blockDim = dim3(256);
        cfg.dynamicSmemBytes = smem1;
        cfg.stream = 0;
        cudaLaunchAttribute attr[1];
        attr[0].id = cudaLaunchAttributeProgrammaticStreamSerialization;
        attr[0].val.programmaticStreamSerializationAllowed = 1;
        cfg.attrs = attr;
        cfg.numAttrs = 1;
        cudaLaunchKernelEx(&cfg, k1, p1);
    }

    // k2 with PDL (overlaps k1 — k1 triggers after its dependency sync)
    {
        cudaLaunchConfig_t cfg = {};
        cfg.gridDim = dim3(NPTS/64);
        cfg.blockDim = dim3(512);
        cfg.dynamicSmemBytes = smem2;
        cfg.stream = 0;
        cudaLaunchAttribute attr[1];
        attr[0].id = cudaLaunchAttributeProgrammaticStreamSerialization;
        attr[0].val.programmaticStreamSerializationAllowed = 1;
        cfg.attrs = attr;
        cfg.numAttrs = 1;
        cudaLaunchKernelEx(&cfg, k2, p2);
    }
}

// round 15
// speedup vs baseline: 1.0151x; 1.0149x over previous
#include <cuda_runtime.h>
#include <cuda_fp16.h>
#include <math.h>

// Problem constants
#define BB   8
#define NN   16384
#define KK   16
#define CC   64
#define MM   32
#define HH   32
#define HID  128
#define NPTS (BB*NN)          // 131072
#define BN_EPS 1e-5f

typedef unsigned long long u64;

__device__ __forceinline__ float gelu_exact(float y) {
    return 0.5f * y * (1.0f + erff(y * 0.70710678118654752f));
}

__device__ __forceinline__ unsigned h2u(__half2 h) { return *(unsigned*)&h; }
__device__ __forceinline__ __half2 u2h(unsigned u) { return *(__half2*)&u; }

__device__ __forceinline__ unsigned smem_u32(const void* p_) {
    unsigned r;
    asm("{ .reg .u64 t; cvta.to.shared.u64 t, %1; cvt.u32.u64 %0, t; }"
        : "=r"(r) : "l"(p_));
    return r;
}
__device__ __forceinline__ void cp_async16(unsigned saddr, const void* gptr) {
    asm volatile("cp.async.cg.shared.global [%0], [%1], 16;"
                 :: "r"(saddr), "l"(gptr));
}
#define CP_COMMIT() asm volatile("cp.async.commit_group;" ::: "memory")
#define CP_WAIT0()  asm volatile("cp.async.wait_group 0;" ::: "memory")

// Packed fp32x2 FMA
#define FFMA2(d,a,b,c) asm("fma.rn.f32x2 %0, %1, %2, %3;" : "=l"(d) : "l"(a), "l"(b), "l"(c))
#define PACK2(d,lo,hi) asm("mov.b64 %0, {%1, %2};" : "=l"(d) : "f"(lo), "f"(hi))
#define UNPK2(lo,hi,d) asm("mov.b64 {%0, %1}, %2;" : "=f"(lo), "=f"(hi) : "l"(d))
union F4 { float4 v; u64 p[2]; };

// m16n8k16 fp16 MMA, fp32 accumulate
__device__ __forceinline__ void mma16816(float d[4], const unsigned a[4],
                                         unsigned b0, unsigned b1) {
    asm volatile("mma.sync.aligned.m16n8k16.row.col.f32.f16.f16.f32 "
        "{%0,%1,%2,%3}, {%4,%5,%6,%7}, {%8,%9}, {%0,%1,%2,%3};"
        : "+f"(d[0]), "+f"(d[1]), "+f"(d[2]), "+f"(d[3])
        : "r"(a[0]), "r"(a[1]), "r"(a[2]), "r"(a[3]), "r"(b0), "r"(b1));
}

// Scratch
__device__ __half g_f12[(size_t)NPTS*128];
__device__ float  g_base[(size_t)NPTS*CC];

// Pre-converted weights + folded params (layouts as R12)
__device__ __half g_k1w[16384];
__device__ __half g_k2w[17920];
__device__ float  g_par1[1536];
__device__ float  g_par2[320];

struct P0 {
    const float *dirv, *de_w1, *de_g1, *de_b1, *de_m1, *de_v1, *de_w2, *de_bias2;
    const float *w1, *b1, *w2, *b2, *w3, *b3;
    const float *agg_g, *agg_b, *agg_m, *agg_v;
    const float *mw1, *mg, *mb, *mm, *mv, *mw2;
};

struct P1 { const float *f, *dp; };
struct P2 { const int* qidx; float* out; };

// ---------------------------------------------------------------------------
// Kernel 0: one-time weight conversion + BN folding.
// ---------------------------------------------------------------------------
__global__ void k0(P0 p) {
    const int tid = blockIdx.x*blockDim.x + threadIdx.x;
    const int stride = gridDim.x*blockDim.x;
    for (int idx = tid; idx < 4096; idx += stride) {
        int c = idx >> 6, i = idx & 63;
        g_k1w[c*72+i]         = __float2half(p.w1[idx]);
        g_k1w[4608 + c*72+i]  = __float2half(p.w2[idx]);
        g_k1w[9216 + c*72+i]  = __float2half(p.w3[idx]);
    }
    for (int idx = tid; idx < 2048; idx += stride) {
        int c = idx >> 5, h = idx & 31;
        g_k1w[13824 + c*40+h] = __float2half(p.de_w2[idx]);
    }
    for (int idx = tid; idx < 8192; idx += stride) {
        int j = idx >> 6, i = idx & 63;
        g_k2w[j*72 + i] = __float2half(p.mw1[idx]);
    }
    for (int idx = tid; idx < 8192; idx += stride) {
        int c = idx >> 7, j = idx & 127;
        g_k2w[9216 + c*136 + j] = __float2half(p.mw2[idx]);
    }
    for (int idx = tid; idx < 1024; idx += stride) {
        int m = idx >> 5, j = idx & 31;
        g_par1[m*32 + j] = p.de_w1[j*32 + m];
    }
    if (tid < 16) {
        int m0 = 2*tid, m1 = m0 + 1;
        float a0=p.dirv[m0*3], a1=p.dirv[m0*3+1], a2=p.dirv[m0*3+2];
        float ia = rsqrtf(fmaxf(a0*a0+a1*a1+a2*a2, 1e-24f));
        float b0=p.dirv[m1*3], b1=p.dirv[m1*3+1], b2=p.dirv[m1*3+2];
        float ib = rsqrtf(fmaxf(b0*b0+b1*b1+b2*b2, 1e-24f));
        unsigned* pv = (unsigned*)g_par1;
        pv[1024 + tid*3 + 0] = h2u(__floats2half2_rn(a0*ia, b0*ib));
        pv[1024 + tid*3 + 1] = h2u(__floats2half2_rn(a1*ia, b1*ib));
        pv[1024 + tid*3 + 2] = h2u(__floats2half2_rn(a2*ia, b2*ib));
    }
    if (tid >= 32 && tid < 96) {
        int c = tid - 32;
        g_par1[1088+c]=p.b1[c];
        g_par1[1152+c]=p.b2[c];
        g_par1[1216+c]=p.b3[c];
        g_par1[1280+c]=p.de_bias2[c];
        float sc = p.agg_g[c]*rsqrtf(p.agg_v[c]+BN_EPS);
        g_par1[1408+c]=sc;
        g_par1[1472+c]=p.agg_b[c]-p.agg_m[c]*sc;
        g_par2[256+c]=sc;
    }
    if (tid >= 96 && tid < 128) {
        int j = tid - 96;
        float sc = p.de_g1[j]*rsqrtf(p.de_v1[j]+BN_EPS);
        g_par1[1344+j]=sc;
        g_par1[1376+j]=p.de_b1[j]-p.de_m1[j]*sc;
    }
    if (tid >= 128 && tid < 256) {
        int j = tid - 128;
        float sc = p.mg[j]*rsqrtf(p.mv[j]+BN_EPS);
        g_par2[j]=sc;
        g_par2[128+j]=p.mb[j]-p.mm[j]*sc;
    }
}

// ---------------------------------------------------------------------------
// Kernel 1: 256 threads, 128 points / block, 3 blocks/SM (smem 67584 B).
// Stage 1 split: threads 0-127 do theta+DE-MLP (their point), threads
// 128-255 stage the fp16 x tile concurrently. MMA stage: 8 warps x 1 tile.
// ---------------------------------------------------------------------------
__global__ __launch_bounds__(256, 3) void k1(P1 p) {
    extern __shared__ char smbase[];
    float*    sp     = (float*)smbase;
    float*    sdw1p  = sp;                    // [m*32+j] 1024
    unsigned* svvh   = (unsigned*)sp + 1024;  // 48
    float*    sb1    = sp + 1088;
    float*    sb2    = sp + 1152;
    float*    sb3    = sp + 1216;
    float*    sbias2 = sp + 1280;
    float*    ssc1   = sp + 1344;
    float*    ssh1   = sp + 1376;
    float*    sscA   = sp + 1408;
    float*    sshA   = sp + 1472;             // -> 1536 floats (6144 B)
    __half* xA  = (__half*)(smbase + 6144);   // 128*72 = 18432 B
    __half* hA  = xA  + 9216;                 // 128*40 = 10240 B
    __half* ws1 = hA  + 5120;                 // weights 32768 B
    __half* ws2 = ws1 + 4608;
    __half* ws3 = ws2 + 4608;
    __half* dws = ws3 + 4608;                 // total 67584 B

    const int tid = threadIdx.x;
    const int p0 = blockIdx.x*128;
    const int b  = p0 >> 14;
    const int n0 = p0 & (NN-1);

    // weights: non-blocking cp.async (32 KB); params synchronously
    {
        unsigned wd = smem_u32(ws1) + tid*16;
        const char* ws = (const char*)g_k1w + tid*16;
#pragma unroll
        for (int i = 0; i < 8; i++)
            cp_async16(wd + i*4096, ws + i*4096);
        CP_COMMIT();
        const float4* ps = (const float4*)g_par1;
        float4* pd = (float4*)sp;
        pd[tid] = ps[tid];
        if (tid < 128) pd[256+tid] = ps[256+tid];
    }
    __syncthreads();   // params visible; weights in flight

    if (tid < 128) {
        // ---- theta_max (packed fp16, 2 k-halves) + DE hidden MLP (FFMA2) ----
        const int n = n0 + tid;
        __half2 acc[16];
        const __half2 NEGH = __float2half2_rn(-65504.f);
#pragma unroll
        for (int pr = 0; pr < 16; pr++) acc[pr] = NEGH;
        const float4* dp4 = (const float4*)(p.dp + (size_t)b*3*NN*KK + (size_t)n*KK);
#pragma unroll
        for (int kh = 0; kh < 2; kh++) {
            unsigned X0[8], X1[8], X2[8];
#pragma unroll
            for (int k4 = 0; k4 < 2; k4++) {
                float4 A = dp4[kh*2 + k4];
                float4 Bv= dp4[(NN*KK/4) + kh*2 + k4];
                float4 Cv= dp4[(2*NN*KK/4) + kh*2 + k4];
                float ax[4]={A.x,A.y,A.z,A.w}, bx[4]={Bv.x,Bv.y,Bv.z,Bv.w}, cx[4]={Cv.x,Cv.y,Cv.z,Cv.w};
#pragma unroll
                for (int kk = 0; kk < 4; kk++) {
                    float x0=ax[kk], x1=bx[kk], x2=cx[kk];
                    float inv = rsqrtf(fmaxf(x0*x0+x1*x1+x2*x2, 1e-24f));
                    X0[4*k4+kk] = h2u(__float2half2_rn(x0*inv));
                    X1[4*k4+kk] = h2u(__float2half2_rn(x1*inv));
                    X2[4*k4+kk] = h2u(__float2half2_rn(x2*inv));
                }
            }
#pragma unroll
            for (int pr = 0; pr < 16; pr++) {
                __half2 v0 = u2h(svvh[pr*3+0]);
                __half2 v1 = u2h(svvh[pr*3+1]);
                __half2 v2 = u2h(svvh[pr*3+2]);
                __half2 a = acc[pr];
#pragma unroll
                for (int k = 0; k < 8; k++) {
                    __half2 d = __hfma2(v2, u2h(X2[k]),
                                 __hfma2(v1, u2h(X1[k]),
                                  __hmul2(v0, u2h(X0[k]))));
                    a = __hmax2(a, d);
                }
                acc[pr] = a;
            }
        }
        float tm[MM];
#pragma unroll
        for (int pr = 0; pr < 16; pr++) {
            float2 t = __half22float2(acc[pr]);
            tm[2*pr] = t.x; tm[2*pr+1] = t.y;
        }

        u64 accp[16];
#pragma unroll
        for (int q = 0; q < 16; q++) accp[q] = 0ull;
#pragma unroll
        for (int m = 0; m < MM; m++) {
            u64 xd; PACK2(xd, tm[m], tm[m]);
            const float4* wrow = (const float4*)&sdw1p[m*32];
#pragma unroll
            for (int q4 = 0; q4 < 8; q4++) {
                F4 wv; wv.v = wrow[q4];
                FFMA2(accp[2*q4  ], wv.p[0], xd, accp[2*q4  ]);
                FFMA2(accp[2*q4+1], wv.p[1], xd, accp[2*q4+1]);
            }
        }
#pragma unroll
        for (int pr = 0; pr < 16; pr++) {
            float a0, a1; UNPK2(a0, a1, accp[pr]);
            int j0 = 2*pr;
            float y0 = a0*ssc1[j0  ] + ssh1[j0  ];
            float y1 = a1*ssc1[j0+1] + ssh1[j0+1];
            *(unsigned*)&hA[tid*40 + j0] =
                h2u(__floats2half2_rn(gelu_exact(y0), gelu_exact(y1)));
        }
    } else {
        // ---- stage x tile for point (tid-128) ----
        const int lp = tid - 128;
        const float* fb = p.f + (size_t)b*CC*NN + (n0 + lp);
#pragma unroll
        for (int c2 = 0; c2 < 32; c2++) {
            float v0 = fb[(size_t)(2*c2  )*NN];
            float v1 = fb[(size_t)(2*c2+1)*NN];
            *(unsigned*)&xA[lp*72 + 2*c2] = h2u(__floats2half2_rn(v0, v1));
        }
    }

    CP_WAIT0();        // weights landed
    __syncthreads();

    const int w  = tid >> 5;
    const int lt = tid & 31;
    const int tq = lt >> 2;
    const int tr = lt & 3;
    const float* fg = p.f + (size_t)b*CC*NN;

    // ---- MMA stage: each warp one 16-point tile ----
    {
        const int ptb = w * 16;
        unsigned ax[4][4], ah[2][4];
#pragma unroll
        for (int ks = 0; ks < 4; ks++) {
            int r0 = (ptb + tq)*72, r1 = r0 + 8*72;
            int k0v = 16*ks + 2*tr;
            ax[ks][0] = *(const unsigned*)&xA[r0 + k0v];
            ax[ks][1] = *(const unsigned*)&xA[r1 + k0v];
            ax[ks][2] = *(const unsigned*)&xA[r0 + k0v + 8];
            ax[ks][3] = *(const unsigned*)&xA[r1 + k0v + 8];
        }
#pragma unroll
        for (int ks = 0; ks < 2; ks++) {
            int r0 = (ptb + tq)*40, r1 = r0 + 8*40;
            int k0v = 16*ks + 2*tr;
            ah[ks][0] = *(const unsigned*)&hA[r0 + k0v];
            ah[ks][1] = *(const unsigned*)&hA[r1 + k0v];
            ah[ks][2] = *(const unsigned*)&hA[r0 + k0v + 8];
            ah[ks][3] = *(const unsigned*)&hA[r1 + k0v + 8];
        }

#pragma unroll 1
        for (int nt = 0; nt < 8; nt++) {
            const int ch0 = nt*8 + tr*2;
            float d1[4], d2[4], d3[4], dpe[4];
            d1[0]=sb1[ch0];   d1[1]=sb1[ch0+1];   d1[2]=d1[0];  d1[3]=d1[1];
            d2[0]=sb2[ch0];   d2[1]=sb2[ch0+1];   d2[2]=d2[0];  d2[3]=d2[1];
            d3[0]=sb3[ch0];   d3[1]=sb3[ch0+1];   d3[2]=d3[0];  d3[3]=d3[1];
            dpe[0]=sbias2[ch0]; dpe[1]=sbias2[ch0+1]; dpe[2]=dpe[0]; dpe[3]=dpe[1];

            const int nrow = (nt*8 + tq)*72;
#pragma unroll
            for (int ks = 0; ks < 4; ks++) {
                const int kb = 16*ks + 2*tr;
                unsigned b0, b1;
                b0 = *(const unsigned*)&ws1[nrow + kb];
                b1 = *(const unsigned*)&ws1[nrow + kb + 8];
                mma16816(d1, ax[ks], b0, b1);
                b0 = *(const unsigned*)&ws2[nrow + kb];
                b1 = *(const unsigned*)&ws2[nrow + kb + 8];
                mma16816(d2, ax[ks], b0, b1);
                b0 = *(const unsigned*)&ws3[nrow + kb];
                b1 = *(const unsigned*)&ws3[nrow + kb + 8];
                mma16816(d3, ax[ks], b0, b1);
            }
            const int drow = (nt*8 + tq)*40;
#pragma unroll
            for (int ks = 0; ks < 2; ks++) {
                const int kb = 16*ks + 2*tr;
                unsigned b0 = *(const unsigned*)&dws[drow + kb];
                unsigned b1 = *(const unsigned*)&dws[drow + kb + 8];
                mma16816(dpe, ah[ks], b0, b1);
            }

#pragma unroll
            for (int r = 0; r < 2; r++) {
                const int lpt = ptb + tq + 8*r;
                const int gpt = p0 + lpt;
                float f1a=d1[2*r], f1b=d1[2*r+1];
                float f2a=d2[2*r], f2b=d2[2*r+1];
                float f3a=d3[2*r], f3b=d3[2*r+1];
                float pea=dpe[2*r], peb=dpe[2*r+1];

                uint2 pk;
                pk.x = h2u(__floats2half2_rn(f1a, f1b));
                pk.y = h2u(__floats2half2_rn(f2a, f2b));
                *(uint2*)(g_f12 + (size_t)gpt*128 + 2*ch0) = pk;

                float fo0 = fg[(size_t)(ch0  )*NN + (n0 + lpt)];
                float fo1 = fg[(size_t)(ch0+1)*NN + (n0 + lpt)];
                float bx = fo0 + pea + sscA[ch0  ]*(f2a+f3a) + sshA[ch0  ];
                float by = fo1 + peb + sscA[ch0+1]*(f2b+f3b) + sshA[ch0+1];
                *(float2*)(g_base + (size_t)gpt*CC + ch0) = make_float2(bx, by);
            }
        }
    }
}

// ---------------------------------------------------------------------------
// Kernel 2 (R12 version): 64 points / block, 512 threads, 2 blocks/SM.
// ---------------------------------------------------------------------------
__global__ __launch_bounds__(512, 2) void k2(P2 p) {
    extern __shared__ char smb[];
    float*  sxs  = (float*)smb;
    float*  sscM = sxs + 4352;
    float*  sshM = sscM + 128;
    float*  sA   = sshM + 128;                   // -> 18688 B
    __half* xh   = (__half*)(smb + 18688);
    __half* h2h  = xh + 4608;
    __half* w1h  = h2h + 8704;
    __half* w2h  = w1h + 9216;                   // -> 81152 B

    const int tid = threadIdx.x;
    const int w = tid >> 5, l = tid & 31;

    {
        unsigned wd = smem_u32(w1h) + tid*16;
        const char* ws = (const char*)g_k2w + tid*16;
#pragma unroll
        for (int i = 0; i < 4; i++)
            cp_async16(wd + i*8192, ws + i*8192);
        if (tid < 192) cp_async16(wd + 4*8192, ws + 4*8192);
        CP_COMMIT();
        const float4* ps = (const float4*)g_par2;
        float4* pd = (float4*)sscM;
        if (tid < 80) pd[tid] = ps[tid];
    }
    __syncthreads();

    const int p0 = blockIdx.x*64;
    const int b  = p0 >> 14;
    const int n0 = p0 & (NN-1);

    // ---- Phase A: paired-point gather + edge max ----
    {
        const int half = (l >> 4) & 1;
        const int c    = l & 15;
        const size_t brow = (size_t)b*NN;
        const __half2 NEG = __float2half2_rn(-65504.f);
        const int lpA0 = w*4,     lp0 = lpA0 + half;
        const int lpA1 = w*4 + 2, lp1 = lpA1 + half;
        int jreg0 = p.qidx[(size_t)(p0 + lpA0)*KK + l];
        int jreg1 = p.qidx[(size_t)(p0 + lpA1)*KK + l];
        uint4 cv0 = *(const uint4*)(g_f12 + ((size_t)(p0+lp0) << 7) + c*8);
        uint4 cv1 = *(const uint4*)(g_f12 + ((size_t)(p0+lp1) << 7) + c*8);
        float4 bs0 = *(const float4*)(g_base + (size_t)(p0+lp0)*CC + 4*c);
        float4 bs1 = *(const float4*)(g_base + (size_t)(p0+lp1)*CC + 4*c);
        float4 sc = *(const float4*)&sA[4*c];
#pragma unroll
        for (int i = 0; i < 2; i++) {
            const int lp = (i == 0) ? lp0 : lp1;
            int jreg = (i == 0) ? jreg0 : jreg1;
            uint4 cv = (i == 0) ? cv0 : cv1;
            float4 bs = (i == 0) ? bs0 : bs1;
            __half2 m1a = NEG, m2a = NEG, m1b = NEG, m2b = NEG;
#pragma unroll
            for (int r = 0; r < KK; r++) {
                int j = __shfl_sync(0xffffffffu, jreg, (l & 16) + r);
                uint4 v = *(const uint4*)(g_f12 + ((brow + (size_t)j) << 7) + c*8);
                m1a = __hmax2(m1a, *(__half2*)&v.x);
                m2a = __hmax2(m2a, *(__half2*)&v.y);
                m1b = __hmax2(m1b, *(__half2*)&v.z);
                m2b = __hmax2(m2b, *(__half2*)&v.w);
            }
            float2 c1a = __half22float2(*(__half2*)&cv.x);
            float2 c2a = __half22float2(*(__half2*)&cv.y);
            float2 c1b = __half22float2(*(__half2*)&cv.z);
            float2 c2b = __half22float2(*(__half2*)&cv.w);
            float2 M1a = __half22float2(m1a), M2a = __half22float2(m2a);
            float2 M1b = __half22float2(m1b), M2b = __half22float2(m2b);
            float v0 = bs.x + sc.x*((M1a.x - c1a.x) + (M2a.x - c2a.x));
            float v1 = bs.y + sc.y*((M1a.y - c1a.y) + (M2a.y - c2a.y));
            float v2 = bs.z + sc.z*((M1b.x - c1b.x) + (M2b.x - c2b.x));
            float v3 = bs.w + sc.w*((M1b.y - c1b.y) + (M2b.y - c2b.y));
            *(float4*)&sxs[lp*68 + 4*c] = make_float4(v0,v1,v2,v3);
            uint2 xp;
            xp.x = h2u(__floats2half2_rn(v0, v1));
            xp.y = h2u(__floats2half2_rn(v2, v3));
            *(uint2*)&xh[lp*72 + 4*c] = xp;
        }
    }
    CP_WAIT0();
    __syncthreads();

    const int tq = l >> 2, tr = l & 3;

    // ---- Phase B: h2 = gelu(bnM(mw1 @ x)) via HMMA ----
    {
        const int pw = w & 3;
        const int nb = w >> 2;
        const int ptb = pw*16;
        unsigned ax[4][4];
#pragma unroll
        for (int ks = 0; ks < 4; ks++) {
            int r0 = (ptb + tq)*72, r1 = r0 + 8*72;
            int k0v = 16*ks + 2*tr;
            ax[ks][0] = *(const unsigned*)&xh[r0 + k0v];
            ax[ks][1] = *(const unsigned*)&xh[r1 + k0v];
            ax[ks][2] = *(const unsigned*)&xh[r0 + k0v + 8];
            ax[ks][3] = *(const unsigned*)&xh[r1 + k0v + 8];
        }
#pragma unroll
        for (int nt = 0; nt < 4; nt++) {
            const int jr = nb*32 + nt*8;
            float d[4] = {0.f,0.f,0.f,0.f};
            const int nrow = (jr + tq)*72;
#pragma unroll
            for (int ks = 0; ks < 4; ks++) {
                const int kb = 16*ks + 2*tr;
                unsigned b0 = *(const unsigned*)&w1h[nrow + kb];
                unsigned b1 = *(const unsigned*)&w1h[nrow + kb + 8];
                mma16816(d, ax[ks], b0, b1);
            }
            const int j0 = jr + 2*tr;
            float sc0 = sscM[j0], sh0 = sshM[j0];
            float sc1 = sscM[j0+1], sh1 = sshM[j0+1];
            float g0 = gelu_exact(d[0]*sc0 + sh0);
            float g1 = gelu_exact(d[1]*sc1 + sh1);
            float g2 = gelu_exact(d[2]*sc0 + sh0);
            float g3 = gelu_exact(d[3]*sc1 + sh1);
            *(unsigned*)&h2h[(ptb+tq  )*136 + j0] = h2u(__floats2half2_rn(g0, g1));
            *(unsigned*)&h2h[(ptb+tq+8)*136 + j0] = h2u(__floats2half2_rn(g2, g3));
        }
    }
    __syncthreads();

    // ---- Phase C: out = x + mw2 @ h2 via HMMA ----
    {
        const int pw = w & 3;
        const int cb = w >> 2;
        const int ptb = pw*16;
        const size_t obase = (size_t)b*CC*NN;
#pragma unroll
        for (int nt = 0; nt < 2; nt++) {
            const int ch = cb*16 + nt*8;
            float d[4] = {0.f,0.f,0.f,0.f};
            const int nrow = (ch + tq)*136;
#pragma unroll
            for (int ks = 0; ks < 8; ks++) {
                const int k0v = 16*ks + 2*tr;
                unsigned a[4];
                int r0 = (ptb + tq)*136, r1 = r0 + 8*136;
                a[0] = *(const unsigned*)&h2h[r0 + k0v];
                a[1] = *(const unsigned*)&h2h[r1 + k0v];
                a[2] = *(const unsigned*)&h2h[r0 + k0v + 8];
                a[3] = *(const unsigned*)&h2h[r1 + k0v + 8];
                unsigned b0 = *(const unsigned*)&w2h[nrow + k0v];
                unsigned b1 = *(const unsigned*)&w2h[nrow + k0v + 8];
                mma16816(d, a, b0, b1);
            }
            const int c0 = ch + 2*tr;
            float x00 = sxs[(ptb+tq  )*68 + c0];
            float x01 = sxs[(ptb+tq  )*68 + c0+1];
            float x10 = sxs[(ptb+tq+8)*68 + c0];
            float x11 = sxs[(ptb+tq+8)*68 + c0+1];
            p.out[obase + (size_t)(c0  )*NN + n0 + ptb+tq  ] = x00 + d[0];
            p.out[obase + (size_t)(c0+1)*NN + n0 + ptb+tq  ] = x01 + d[1];
            p.out[obase + (size_t)(c0  )*NN + n0 + ptb+tq+8] = x10 + d[2];
            p.out[obase + (size_t)(c0+1)*NN + n0 + ptb+tq+8] = x11 + d[3];
        }
    }
}

// ---------------------------------------------------------------------------
extern "C" void kernel_launch(void* const* d_in, const int* in_sizes, int n_in,
                              void* d_out, int out_size) {
    const float* f        = (const float*)d_in[0];
    const float* dp       = (const float*)d_in[1];
    const int*   qidx     = (const int*)  d_in[2];
    const float* dirv     = (const float*)d_in[3];
    const float* de_w1    = (const float*)d_in[4];
    const float* de_g1    = (const float*)d_in[5];
    const float* de_b1    = (const float*)d_in[6];
    const float* de_m1    = (const float*)d_in[7];
    const float* de_v1    = (const float*)d_in[8];
    const float* de_w2    = (const float*)d_in[9];
    const float* de_bias2 = (const float*)d_in[10];
    const float* w1       = (const float*)d_in[11];
    const float* b1       = (const float*)d_in[12];
    const float* w2       = (const float*)d_in[13];
    const float* b2       = (const float*)d_in[14];
    const float* w3       = (const float*)d_in[15];
    const float* b3       = (const float*)d_in[16];
    const float* agg_g    = (const float*)d_in[17];
    const float* agg_b    = (const float*)d_in[18];
    const float* agg_m    = (const float*)d_in[19];
    const float* agg_v    = (const float*)d_in[20];
    const float* mw1      = (const float*)d_in[21];
    const float* mg       = (const float*)d_in[22];
    const float* mb       = (const float*)d_in[23];
    const float* mm       = (const float*)d_in[24];
    const float* mv       = (const float*)d_in[25];
    const float* mw2      = (const float*)d_in[26];

    P0 p0;
    p0.dirv=dirv; p0.de_w1=de_w1; p0.de_g1=de_g1; p0.de_b1=de_b1; p0.de_m1=de_m1;
    p0.de_v1=de_v1; p0.de_w2=de_w2; p0.de_bias2=de_bias2;
    p0.w1=w1; p0.b1=b1; p0.w2=w2; p0.b2=b2; p0.w3=w3; p0.b3=b3;
    p0.agg_g=agg_g; p0.agg_b=agg_b; p0.agg_m=agg_m; p0.agg_v=agg_v;
    p0.mg=mg; p0.mb=mb; p0.mm=mm; p0.mv=mv; p0.mw1=mw1; p0.mw2=mw2;

    P1 p1; p1.f=f; p1.dp=dp;
    P2 p2; p2.qidx=qidx; p2.out=(float*)d_out;

    const size_t smem1 = 67584;   // bytes (3 blocks/SM)
    const size_t smem2 = 81152;   // bytes
    cudaFuncSetAttribute(k1, cudaFuncAttributeMaxDynamicSharedMemorySize, (int)smem1);
    cudaFuncSetAttribute(k2, cudaFuncAttributeMaxDynamicSharedMemorySize, (int)smem2);

    k0<<<128, 256>>>(p0);
    k1<<<NPTS/128, 256, smem1>>>(p1);
    k2<<<NPTS/64, 512, smem2>>>(p2);
}